// round 8
// baseline (speedup 1.0000x reference)
#include <cuda_runtime.h>
#include <cstdint>

#define NMAX 100000
#define EMAX 1200000
#define CAP  64   // in-degree capacity; Poisson(12) => P(deg>64) ~ 1e-30, safe

// Scratch (__device__ globals; no allocation allowed). Zero-initialized at load.
__device__ float g_h [(size_t)NMAX * 64];
__device__ float g_hb[(size_t)NMAX * 64];
__device__ int   g_bucket[(size_t)NMAX * CAP];
__device__ int   g_cnt[NMAX];

__device__ __forceinline__ float group8_sum(float v) {
#pragma unroll
    for (int o = 4; o; o >>= 1) v += __shfl_xor_sync(0xffffffffu, v, o);
    return v;
}

// Histogram + bucket fill: cnt[d] = in-degree, bucket[d*CAP + 0..deg) = src ids.
__global__ __launch_bounds__(256) void fill_k(
    const int* __restrict__ src, const int* __restrict__ dst, int E)
{
    int e = blockIdx.x * 256 + threadIdx.x;
    if (e >= E) return;
    int d = __ldg(dst + e);
    int s = __ldg(src + e);
    int pos = atomicAdd(&g_cnt[d], 1);
    if (pos < CAP) g_bucket[(size_t)d * CAP + pos] = s;
}

// Stage bucket rows for the warp's 4 nodes into shared (ish stride 68 ints:
// bank offset 4g per group + int4 alignment). 2 guarded coalesced LDG.128.
__device__ __forceinline__ void stage_ids(
    int* __restrict__ ish, int n0, int m, int lane)
{
#pragma unroll
    for (int it = 0; it < 2; it++) {
        int t = lane + it * 32;
        int nodei = t >> 4;               // 0..3
        int s4    = (t & 15) << 2;        // slot base 0,4,..,60
        int mi = __shfl_sync(0xffffffffu, m, nodei << 3);
        if (s4 < mi) {
            int4 v = __ldg((const int4*)(g_bucket + (size_t)(n0 + nodei) * CAP)
                           + (t & 15));
            *(int4*)&ish[nodei * 68 + s4] = v;
        }
    }
    __syncwarp();
}

// Gather-sum of h rows whose ids are staged in ish[g*68 + .]. Lane `sub` owns
// channels [8*sub,8*sub+8) as two float4s. Ids arrive via broadcast LDS.128
// (4 slots at a time) -> zero L1tex traffic for the id stream.
__device__ __forceinline__ void gather_node(
    const float* __restrict__ hsrc, const int* __restrict__ ish,
    int g, int m, int mw, int sub, float4& ua, float4& ub)
{
    const float4* h4 = (const float4*)hsrc;
    ua = make_float4(0.f, 0.f, 0.f, 0.f);
    ub = ua;
    for (int j = 0; j < mw; j += 4) {
        int4 s4v = *(const int4*)&ish[g * 68 + j];   // LDS.128, conflict-free
        int sid[4] = { s4v.x, s4v.y, s4v.z, s4v.w };
#pragma unroll
        for (int q = 0; q < 4; q++) {
            if (j + q < m) {
                const float4* r = h4 + (size_t)sid[q] * 16 + sub * 2;
                float4 va = __ldg(r);                // LDG.128: 512B/warp-instr
                float4 vb = __ldg(r + 1);
                ua.x += va.x; ua.y += va.y; ua.z += va.z; ua.w += va.w;
                ub.x += vb.x; ub.y += vb.y; ub.z += vb.z; ub.w += vb.w;
            }
        }
    }
}

// MODE 0: x = emb -> logmap0 -> GEMM(W1,b1) -> g_h
// MODE 1: u = mean(gather g_h) -> expmap0 -> logmap0 -> GEMM(W2,b2) -> g_hb
// 4 nodes per warp (8-lane groups); 8 warps per block.
// GEMM uses packed fp32 FFMA2 (fma.rn.f32x2): the two NODES of a pair share a
// 64-bit register; (t0[k],t1[k]) loads directly as u64 from the float4 tangent
// layout, only w needs a mov.b64 duplicate. Bit-exact fp32.
template <int MODE>
__global__ __launch_bounds__(256) void layer_k(
    const float* __restrict__ xin,
    const float* __restrict__ W,
    const float* __restrict__ b,
    const float* __restrict__ curv,
    int n)
{
    __shared__ float2 Ws2[64 * 33];   // W^T staged: float2 (j=2*lane..+1) per k, padded
    __shared__ float2 bsh[32];
    __shared__ __align__(16) float4 tsh[8 * 72];  // t[k] per node, pad every 8 k
    __shared__ __align__(16) int    ish[8][272];  // staged bucket ids (stride 68)

    int tid = threadIdx.x;
    float* Wf = (float*)Ws2;          // float index k*66 + j
    for (int idx = tid; idx < 64 * 64; idx += 256) {
        int j = idx >> 6, k = idx & 63;     // W[j,k] row-major
        Wf[k * 66 + j] = W[idx];
    }
    if (tid < 32) bsh[tid] = ((const float2*)b)[tid];
    __syncthreads();

    int lane = tid & 31, wid = tid >> 5;
    int g = lane >> 3, sub = lane & 7;
    int n0 = (blockIdx.x * 8 + wid) * 4;
    if (n0 >= n) return;
    int node = n0 + g;

    float sc = sqrtf(fabsf(curv[0]));

    float4 ua, ub;           // lane's 8 channels of this node's vector
    float  pre;              // scalar factor raw->tangent

    if (MODE == 0) {
        int nd = node < n ? node : n - 1;
        const float4* x4 = (const float4*)xin + (size_t)nd * 16 + sub * 2;
        ua = __ldg(x4); ub = __ldg(x4 + 1);
        float d8 = group8_sum(ua.x*ua.x + ua.y*ua.y + ua.z*ua.z + ua.w*ua.w +
                              ub.x*ub.x + ub.y*ub.y + ub.z*ub.z + ub.w*ub.w);
        float nx  = fmaxf(sqrtf(d8), 1e-15f);
        float arg = fminf(sc * nx, 1.0f - 1e-7f);
        pre = atanhf(arg) / (sc * nx);
    } else {
        int deg = (node < n) ? g_cnt[node] : 0;
        int m   = min(deg, CAP);
        int mw  = __reduce_max_sync(0xffffffffu, m);
        stage_ids(ish[wid], n0, m, lane);
        gather_node(g_h, ish[wid], g, m, mw, sub, ua, ub);
        float inv = deg > 0 ? 1.f / (float)deg : 0.f;
        float d8  = group8_sum(ua.x*ua.x + ua.y*ua.y + ua.z*ua.z + ua.w*ua.w +
                               ub.x*ub.x + ub.y*ub.y + ub.z*ub.z + ub.w*ub.w);
        float r   = sqrtf(d8);                       // ||u_raw||
        float un  = fmaxf(r * inv, 1e-15f);          // ||u_raw/deg||
        float fe  = tanhf(sc * un) / (sc * un);      // expmap0 factor
        pre = inv * fe;                              // x = pre * u_raw
        float nx  = fmaxf(r * pre, 1e-15f);          // ||x|| = pre * r
        float arg = fminf(sc * nx, 1.0f - 1e-7f);
        float gf  = atanhf(arg) / (sc * nx);
        pre *= gf;                                   // t = pre * u_raw
    }

    // Tangent to shared: t[k] for node g at float4 index (k + k/8), comp g.
    // Lane covers k = 8*sub + i -> float offset 36*sub + 4*i + g (32 distinct
    // banks per i: sub strides 4 mod 32, g strides 1).
    {
        float* tp = (float*)(tsh + wid * 72);
        float t[8] = { pre*ua.x, pre*ua.y, pre*ua.z, pre*ua.w,
                       pre*ub.x, pre*ub.y, pre*ub.z, pre*ub.w };
#pragma unroll
        for (int i = 0; i < 8; i++) tp[36 * sub + 4 * i + g] = t[i];
    }
    __syncwarp();

    // GEMM: h[j] = b[j] + sum_k t[k]*W[j,k]; lane covers j0=2*lane, j1=2*lane+1.
    // accA=(n0,n1)@j0  accB=(n2,n3)@j0  accC=(n0,n1)@j1  accD=(n2,n3)@j1
    float2 bb2 = bsh[lane];
    unsigned long long accA, accB, accC, accD;
    asm("mov.b64 %0, {%1,%1};" : "=l"(accA) : "f"(bb2.x));
    asm("mov.b64 %0, {%1,%1};" : "=l"(accC) : "f"(bb2.y));
    accB = accA;
    accD = accC;

    uint32_t tbase = (uint32_t)__cvta_generic_to_shared(tsh + wid * 72);
#pragma unroll
    for (int k = 0; k < 64; k++) {
        unsigned long long t01, t23, wxx, wyy;
        asm("ld.shared.v2.u64 {%0,%1}, [%2];"
            : "=l"(t01), "=l"(t23) : "r"(tbase + (k + (k >> 3)) * 16));
        float2 w = Ws2[k * 33 + lane];               // conflict-free LDS.64
        asm("mov.b64 %0, {%1,%1};" : "=l"(wxx) : "f"(w.x));
        asm("mov.b64 %0, {%1,%1};" : "=l"(wyy) : "f"(w.y));
        asm("fma.rn.f32x2 %0, %1, %2, %0;" : "+l"(accA) : "l"(t01), "l"(wxx));
        asm("fma.rn.f32x2 %0, %1, %2, %0;" : "+l"(accB) : "l"(t23), "l"(wxx));
        asm("fma.rn.f32x2 %0, %1, %2, %0;" : "+l"(accC) : "l"(t01), "l"(wyy));
        asm("fma.rn.f32x2 %0, %1, %2, %0;" : "+l"(accD) : "l"(t23), "l"(wyy));
    }

    float2 a0, a1, a2, a3;
    asm("mov.b64 {%0,%1}, %2;" : "=f"(a0.x), "=f"(a1.x) : "l"(accA));
    asm("mov.b64 {%0,%1}, %2;" : "=f"(a2.x), "=f"(a3.x) : "l"(accB));
    asm("mov.b64 {%0,%1}, %2;" : "=f"(a0.y), "=f"(a1.y) : "l"(accC));
    asm("mov.b64 {%0,%1}, %2;" : "=f"(a2.y), "=f"(a3.y) : "l"(accD));

    float2* ho = (float2*)(MODE == 0 ? g_h : g_hb);
    if (n0 + 0 < n) ho[(size_t)(n0 + 0) * 32 + lane] = a0;
    if (n0 + 1 < n) ho[(size_t)(n0 + 1) * 32 + lane] = a1;
    if (n0 + 2 < n) ho[(size_t)(n0 + 2) * 32 + lane] = a2;
    if (n0 + 3 < n) ho[(size_t)(n0 + 3) * 32 + lane] = a3;
}

// Final: out = expmap0(mean(gather g_hb)). Resets g_cnt (each valid node once)
// so every execution leaves g_cnt zeroed, matching load-time init for replay.
__global__ __launch_bounds__(256) void final_k(
    const float* __restrict__ curv, float* __restrict__ out, int n)
{
    __shared__ __align__(16) int ish[8][272];

    int tid = threadIdx.x, lane = tid & 31, wid = tid >> 5;
    int g = lane >> 3, sub = lane & 7;
    int n0 = (blockIdx.x * 8 + wid) * 4;
    if (n0 >= n) return;
    int node = n0 + g;

    float sc  = sqrtf(fabsf(curv[0]));
    int deg   = (node < n) ? g_cnt[node] : 0;
    int m     = min(deg, CAP);
    int mw    = __reduce_max_sync(0xffffffffu, m);

    stage_ids(ish[wid], n0, m, lane);

    float4 ua, ub;
    gather_node(g_hb, ish[wid], g, m, mw, sub, ua, ub);

    float inv = deg > 0 ? 1.f / (float)deg : 0.f;
    float d8  = group8_sum(ua.x*ua.x + ua.y*ua.y + ua.z*ua.z + ua.w*ua.w +
                           ub.x*ub.x + ub.y*ub.y + ub.z*ub.z + ub.w*ub.w);
    float un  = fmaxf(sqrtf(d8) * inv, 1e-15f);
    float fe  = tanhf(sc * un) / (sc * un);
    float s   = inv * fe;

    if (node < n) {
        float4* o4 = (float4*)out + (size_t)node * 16 + sub * 2;
        o4[0] = make_float4(s*ua.x, s*ua.y, s*ua.z, s*ua.w);
        o4[1] = make_float4(s*ub.x, s*ub.y, s*ub.z, s*ub.w);
        if (sub == 0) g_cnt[node] = 0;   // leave zeroed for next replay
    }
}

extern "C" void kernel_launch(void* const* d_in, const int* in_sizes, int n_in,
                              void* d_out, int out_size)
{
    const int*   src  = (const int*)d_in[0];
    const int*   dst  = (const int*)d_in[1];
    const float* emb  = (const float*)d_in[2];
    const float* W1   = (const float*)d_in[3];
    const float* b1   = (const float*)d_in[4];
    const float* W2   = (const float*)d_in[5];
    const float* b2   = (const float*)d_in[6];
    const float* curv = (const float*)d_in[7];
    float* out = (float*)d_out;

    int E = in_sizes[0];
    int N = in_sizes[2] / 64;
    if (N > NMAX) N = NMAX;
    if (E > EMAX) E = EMAX;

    int edge_blocks = (E + 255) / 256;
    int node_blocks = (N + 31) / 32;    // 8 warps x 4 nodes per block

    fill_k    <<<edge_blocks, 256>>>(src, dst, E);
    layer_k<0><<<node_blocks, 256>>>(emb, W1, b1, curv, N);
    layer_k<1><<<node_blocks, 256>>>(nullptr, W2, b2, curv, N);
    final_k   <<<node_blocks, 256>>>(curv, out, N);
}

// round 9
// speedup vs baseline: 1.0553x; 1.0553x over previous
#include <cuda_runtime.h>
#include <cstdint>

#define NMAX 100000
#define EMAX 1200000
#define CAP  64   // in-degree capacity; Poisson(12) => P(deg>64) ~ 1e-30, safe

// Scratch (__device__ globals; no allocation allowed). Zero-initialized at load.
__device__ float g_h [(size_t)NMAX * 64];
__device__ float g_hb[(size_t)NMAX * 64];
__device__ int   g_bucket[(size_t)NMAX * CAP];
__device__ int   g_cnt[NMAX];

__device__ __forceinline__ float group8_sum(float v) {
#pragma unroll
    for (int o = 4; o; o >>= 1) v += __shfl_xor_sync(0xffffffffu, v, o);
    return v;
}

// Histogram + bucket fill: cnt[d] = in-degree, bucket[d*CAP + 0..deg) = src ids.
__global__ __launch_bounds__(256) void fill_k(
    const int* __restrict__ src, const int* __restrict__ dst, int E)
{
    int e = blockIdx.x * 256 + threadIdx.x;
    if (e >= E) return;
    int d = __ldg(dst + e);
    int s = __ldg(src + e);
    int pos = atomicAdd(&g_cnt[d], 1);
    if (pos < CAP) g_bucket[(size_t)d * CAP + pos] = s;
}

// Stage bucket rows for the warp's 4 nodes into shared (stride 68 ints).
__device__ __forceinline__ void stage_ids(
    int* __restrict__ ish, int n0, int m, int lane)
{
#pragma unroll
    for (int it = 0; it < 2; it++) {
        int t = lane + it * 32;
        int nodei = t >> 4;               // 0..3
        int s4    = (t & 15) << 2;        // slot base 0,4,..,60
        int mi = __shfl_sync(0xffffffffu, m, nodei << 3);
        if (s4 < mi) {
            int4 v = __ldg((const int4*)(g_bucket + (size_t)(n0 + nodei) * CAP)
                           + (t & 15));
            *(int4*)&ish[nodei * 68 + s4] = v;
        }
    }
    __syncwarp();
}

// Gather-sum of h rows whose ids are staged in ish[g*68+.]. COALESCED channel
// map: lane `sub` owns channels [4s,4s+4) and [32+4s,32+4s+4), so each group's
// load covers a contiguous 128B half-row -> 1 line/group/instr (was 2).
// Accumulate packed (add.rn.f32x2): 4 packed adds/slot instead of 8 FADDs.
__device__ __forceinline__ void gather_node(
    const float* __restrict__ hsrc, const int* __restrict__ ish,
    int g, int m, int mw, int sub,
    unsigned long long& ac0, unsigned long long& ac1,
    unsigned long long& ac2, unsigned long long& ac3)
{
    const char* hb = (const char*)hsrc + sub * 16;
    ac0 = ac1 = ac2 = ac3 = 0ull;        // bits of (0.f,0.f)
    for (int j = 0; j < mw; j += 4) {
        int4 s4v = *(const int4*)&ish[g * 68 + j];   // broadcast LDS.128
        int sid[4] = { s4v.x, s4v.y, s4v.z, s4v.w };
#pragma unroll
        for (int q = 0; q < 4; q++) {
            if (j + q < m) {
                const char* p = hb + (size_t)sid[q] * 256;
                unsigned long long a, b, c, d;
                asm("ld.global.nc.v2.u64 {%0,%1}, [%2];"
                    : "=l"(a), "=l"(b) : "l"(p));
                asm("ld.global.nc.v2.u64 {%0,%1}, [%2];"
                    : "=l"(c), "=l"(d) : "l"(p + 128));
                asm("add.rn.f32x2 %0, %0, %1;" : "+l"(ac0) : "l"(a));
                asm("add.rn.f32x2 %0, %0, %1;" : "+l"(ac1) : "l"(b));
                asm("add.rn.f32x2 %0, %0, %1;" : "+l"(ac2) : "l"(c));
                asm("add.rn.f32x2 %0, %0, %1;" : "+l"(ac3) : "l"(d));
            }
        }
    }
}

__device__ __forceinline__ float4 unpack2(unsigned long long a,
                                          unsigned long long b)
{
    float4 r;
    asm("mov.b64 {%0,%1}, %2;" : "=f"(r.x), "=f"(r.y) : "l"(a));
    asm("mov.b64 {%0,%1}, %2;" : "=f"(r.z), "=f"(r.w) : "l"(b));
    return r;
}

// MODE 0: x = emb -> logmap0 -> GEMM(W1,b1) -> g_h
// MODE 1: u = mean(gather g_h) -> expmap0 -> logmap0 -> GEMM(W2,b2) -> g_hb
// 4 nodes per warp (8-lane groups); 8 warps per block. GEMM in packed FFMA2.
template <int MODE>
__global__ __launch_bounds__(256) void layer_k(
    const float* __restrict__ xin,
    const float* __restrict__ W,
    const float* __restrict__ b,
    const float* __restrict__ curv,
    int n)
{
    __shared__ float2 Ws2[64 * 33];   // W^T staged: float2 (j=2*lane..+1) per k, padded
    __shared__ float2 bsh[32];
    __shared__ __align__(16) float4 tsh[8 * 72];           // t[k] per node, padded
    __shared__ __align__(16) int    ish[MODE ? 8 * 272 : 8];  // ids (MODE1 only)

    int tid = threadIdx.x;
    float* Wf = (float*)Ws2;          // float index k*66 + j
    for (int idx = tid; idx < 64 * 64; idx += 256) {
        int j = idx >> 6, k = idx & 63;     // W[j,k] row-major
        Wf[k * 66 + j] = W[idx];
    }
    if (tid < 32) bsh[tid] = ((const float2*)b)[tid];
    __syncthreads();

    int lane = tid & 31, wid = tid >> 5;
    int g = lane >> 3, sub = lane & 7;
    int n0 = (blockIdx.x * 8 + wid) * 4;
    if (n0 >= n) return;
    int node = n0 + g;

    float sc = sqrtf(fabsf(curv[0]));

    float4 ua, ub;   // lane's channels [4sub,4sub+4), [32+4sub,32+4sub+4)
    float  pre;      // scalar factor raw->tangent

    if (MODE == 0) {
        int nd = node < n ? node : n - 1;
        const float4* x4 = (const float4*)xin + (size_t)nd * 16;
        ua = __ldg(x4 + sub);            // first half-row: coalesced per group
        ub = __ldg(x4 + 8 + sub);        // second half-row
        float d8 = group8_sum(ua.x*ua.x + ua.y*ua.y + ua.z*ua.z + ua.w*ua.w +
                              ub.x*ub.x + ub.y*ub.y + ub.z*ub.z + ub.w*ub.w);
        float nx  = fmaxf(sqrtf(d8), 1e-15f);
        float arg = fminf(sc * nx, 1.0f - 1e-7f);
        pre = atanhf(arg) / (sc * nx);
    } else {
        int deg = (node < n) ? g_cnt[node] : 0;
        int m   = min(deg, CAP);
        int mw  = __reduce_max_sync(0xffffffffu, m);
        stage_ids(ish + wid * 272, n0, m, lane);
        unsigned long long ac0, ac1, ac2, ac3;
        gather_node(g_h, ish + wid * 272, g, m, mw, sub, ac0, ac1, ac2, ac3);
        ua = unpack2(ac0, ac1);
        ub = unpack2(ac2, ac3);
        float inv = deg > 0 ? 1.f / (float)deg : 0.f;
        float d8  = group8_sum(ua.x*ua.x + ua.y*ua.y + ua.z*ua.z + ua.w*ua.w +
                               ub.x*ub.x + ub.y*ub.y + ub.z*ub.z + ub.w*ub.w);
        float r   = sqrtf(d8);                       // ||u_raw||
        float un  = fmaxf(r * inv, 1e-15f);          // ||u_raw/deg||
        float fe  = tanhf(sc * un) / (sc * un);      // expmap0 factor
        pre = inv * fe;                              // x = pre * u_raw
        float nx  = fmaxf(r * pre, 1e-15f);          // ||x|| = pre * r
        float arg = fminf(sc * nx, 1.0f - 1e-7f);
        float gf  = atanhf(arg) / (sc * nx);
        pre *= gf;                                   // t = pre * u_raw
    }

    // Tangent to shared (canonical k order): lane's 8 values sit at
    // k = 4*sub+i and 32+4*sub+i; float offset 4*k + 4*(k>>3) + g.
    // Banks per i: 16s+4(s>>1)+g mod 32 = {0,16,4,20,8,24,12,28}+g -> distinct.
    {
        float* tp = (float*)(tsh + wid * 72);
        float ta[4] = { pre*ua.x, pre*ua.y, pre*ua.z, pre*ua.w };
        float tb[4] = { pre*ub.x, pre*ub.y, pre*ub.z, pre*ub.w };
#pragma unroll
        for (int i = 0; i < 4; i++) {
            int k = 4 * sub + i;
            tp[4 * k + 4 * (k >> 3) + g] = ta[i];
            k += 32;
            tp[4 * k + 4 * (k >> 3) + g] = tb[i];
        }
    }
    __syncwarp();

    // GEMM: h[j] = b[j] + sum_k t[k]*W[j,k]; lane covers j0=2*lane, j1=2*lane+1.
    // accA=(n0,n1)@j0  accB=(n2,n3)@j0  accC=(n0,n1)@j1  accD=(n2,n3)@j1
    float2 bb2 = bsh[lane];
    unsigned long long accA, accB, accC, accD;
    asm("mov.b64 %0, {%1,%1};" : "=l"(accA) : "f"(bb2.x));
    asm("mov.b64 %0, {%1,%1};" : "=l"(accC) : "f"(bb2.y));
    accB = accA;
    accD = accC;

    uint32_t tbase = (uint32_t)__cvta_generic_to_shared(tsh + wid * 72);
#pragma unroll
    for (int k = 0; k < 64; k++) {
        unsigned long long t01, t23, wxx, wyy;
        asm("ld.shared.v2.u64 {%0,%1}, [%2];"
            : "=l"(t01), "=l"(t23) : "r"(tbase + (k + (k >> 3)) * 16));
        float2 w = Ws2[k * 33 + lane];               // conflict-free LDS.64
        asm("mov.b64 %0, {%1,%1};" : "=l"(wxx) : "f"(w.x));
        asm("mov.b64 %0, {%1,%1};" : "=l"(wyy) : "f"(w.y));
        asm("fma.rn.f32x2 %0, %1, %2, %0;" : "+l"(accA) : "l"(t01), "l"(wxx));
        asm("fma.rn.f32x2 %0, %1, %2, %0;" : "+l"(accB) : "l"(t23), "l"(wxx));
        asm("fma.rn.f32x2 %0, %1, %2, %0;" : "+l"(accC) : "l"(t01), "l"(wyy));
        asm("fma.rn.f32x2 %0, %1, %2, %0;" : "+l"(accD) : "l"(t23), "l"(wyy));
    }

    float2 a0, a1, a2, a3;
    asm("mov.b64 {%0,%1}, %2;" : "=f"(a0.x), "=f"(a1.x) : "l"(accA));
    asm("mov.b64 {%0,%1}, %2;" : "=f"(a2.x), "=f"(a3.x) : "l"(accB));
    asm("mov.b64 {%0,%1}, %2;" : "=f"(a0.y), "=f"(a1.y) : "l"(accC));
    asm("mov.b64 {%0,%1}, %2;" : "=f"(a2.y), "=f"(a3.y) : "l"(accD));

    float2* ho = (float2*)(MODE == 0 ? g_h : g_hb);
    if (n0 + 0 < n) ho[(size_t)(n0 + 0) * 32 + lane] = a0;
    if (n0 + 1 < n) ho[(size_t)(n0 + 1) * 32 + lane] = a1;
    if (n0 + 2 < n) ho[(size_t)(n0 + 2) * 32 + lane] = a2;
    if (n0 + 3 < n) ho[(size_t)(n0 + 3) * 32 + lane] = a3;
}

// Final: out = expmap0(mean(gather g_hb)). Resets g_cnt (each valid node once)
// so every execution leaves g_cnt zeroed, matching load-time init for replay.
__global__ __launch_bounds__(256) void final_k(
    const float* __restrict__ curv, float* __restrict__ out, int n)
{
    __shared__ __align__(16) int ish[8 * 272];

    int tid = threadIdx.x, lane = tid & 31, wid = tid >> 5;
    int g = lane >> 3, sub = lane & 7;
    int n0 = (blockIdx.x * 8 + wid) * 4;
    if (n0 >= n) return;
    int node = n0 + g;

    float sc  = sqrtf(fabsf(curv[0]));
    int deg   = (node < n) ? g_cnt[node] : 0;
    int m     = min(deg, CAP);
    int mw    = __reduce_max_sync(0xffffffffu, m);

    stage_ids(ish + wid * 272, n0, m, lane);

    unsigned long long ac0, ac1, ac2, ac3;
    gather_node(g_hb, ish + wid * 272, g, m, mw, sub, ac0, ac1, ac2, ac3);
    float4 ua = unpack2(ac0, ac1);
    float4 ub = unpack2(ac2, ac3);

    float inv = deg > 0 ? 1.f / (float)deg : 0.f;
    float d8  = group8_sum(ua.x*ua.x + ua.y*ua.y + ua.z*ua.z + ua.w*ua.w +
                           ub.x*ub.x + ub.y*ub.y + ub.z*ub.z + ub.w*ub.w);
    float un  = fmaxf(sqrtf(d8) * inv, 1e-15f);
    float fe  = tanhf(sc * un) / (sc * un);
    float s   = inv * fe;

    if (node < n) {
        float4* o4 = (float4*)out + (size_t)node * 16;
        o4[sub]     = make_float4(s*ua.x, s*ua.y, s*ua.z, s*ua.w);
        o4[8 + sub] = make_float4(s*ub.x, s*ub.y, s*ub.z, s*ub.w);
        if (sub == 0) g_cnt[node] = 0;   // leave zeroed for next replay
    }
}

extern "C" void kernel_launch(void* const* d_in, const int* in_sizes, int n_in,
                              void* d_out, int out_size)
{
    const int*   src  = (const int*)d_in[0];
    const int*   dst  = (const int*)d_in[1];
    const float* emb  = (const float*)d_in[2];
    const float* W1   = (const float*)d_in[3];
    const float* b1   = (const float*)d_in[4];
    const float* W2   = (const float*)d_in[5];
    const float* b2   = (const float*)d_in[6];
    const float* curv = (const float*)d_in[7];
    float* out = (float*)d_out;

    int E = in_sizes[0];
    int N = in_sizes[2] / 64;
    if (N > NMAX) N = NMAX;
    if (E > EMAX) E = EMAX;

    int edge_blocks = (E + 255) / 256;
    int node_blocks = (N + 31) / 32;    // 8 warps x 4 nodes per block

    fill_k    <<<edge_blocks, 256>>>(src, dst, E);
    layer_k<0><<<node_blocks, 256>>>(emb, W1, b1, curv, N);
    layer_k<1><<<node_blocks, 256>>>(nullptr, W2, b2, curv, N);
    final_k   <<<node_blocks, 256>>>(curv, out, N);
}